// round 1
// baseline (speedup 1.0000x reference)
#include <cuda_runtime.h>
#include <cuda_bf16.h>
#include <math.h>

#define NE    800000
#define NN    50000
#define TILE  64
#define HID   128

// ---------------- scratch (static device globals; no allocation) ----------------
__device__ float4 g_xh4[NN * 32];       // xh = x@W_x + b_x, [N,128] as float4
__device__ float  g_wV [NN * 128];      // scatter-add accumulator
__device__ float  g_deg[NN];            // degree accumulator

// ---------------- helpers ----------------
union U2 { float2 f; unsigned long long u; };

__device__ __forceinline__ float2 ffma2(float2 a, float2 b, float2 c) {
    U2 A, B, C, D; A.f = a; B.f = b; C.f = c;
    asm("fma.rn.f32x2 %0, %1, %2, %3;" : "=l"(D.u) : "l"(A.u), "l"(B.u), "l"(C.u));
    return D.f;
}

// swizzled activation buffer index (float4 quads): k in [0,128), rq in [0,16)
__device__ __forceinline__ int aidx(int k, int rq) {
    return (k << 4) + (rq ^ ((k >> 2) & 7));
}

__device__ __forceinline__ float gelu_f(float x) {
    return 0.5f * x * (1.0f + erff(x * 0.70710678118654752f));
}

// ---------------- fused edge kernel ----------------
// 128 threads: tr = tid>>5 (row group, 16 edges), tc = tid&31 (4 cols).
// Each thread: acc[8][4] packed float2 over row pairs = 16 rows x 4 cols.
__device__ __forceinline__ void gemm_stage(
    float2 acc[8][4], const float4* __restrict__ Wg, int K,
    const float4* sG, float4* sW, int tid, int tr, int tc)
{
#pragma unroll
    for (int rp = 0; rp < 8; rp++)
#pragma unroll
        for (int c = 0; c < 4; c++) acc[rp][c] = make_float2(0.f, 0.f);

    for (int k0 = 0; k0 < K; k0 += 16) {
        int rows = (K - k0 < 16) ? (K - k0) : 16;
        __syncthreads();                       // prior sW readers done
        for (int i = tid; i < rows * 32; i += 128)
            sW[i] = Wg[k0 * 32 + i];
        __syncthreads();
#pragma unroll 4
        for (int kk = 0; kk < rows; kk++) {
            int k = k0 + kk;
            float4 w  = sW[kk * 32 + tc];
            float4 a0 = sG[aidx(k, tr * 4 + 0)];
            float4 a1 = sG[aidx(k, tr * 4 + 1)];
            float4 a2 = sG[aidx(k, tr * 4 + 2)];
            float4 a3 = sG[aidx(k, tr * 4 + 3)];
            float2 wd[4] = { {w.x,w.x}, {w.y,w.y}, {w.z,w.z}, {w.w,w.w} };
            float2 ap[8] = { {a0.x,a0.y},{a0.z,a0.w},{a1.x,a1.y},{a1.z,a1.w},
                             {a2.x,a2.y},{a2.z,a2.w},{a3.x,a3.y},{a3.z,a3.w} };
#pragma unroll
            for (int rp = 0; rp < 8; rp++) {
                acc[rp][0] = ffma2(ap[rp], wd[0], acc[rp][0]);
                acc[rp][1] = ffma2(ap[rp], wd[1], acc[rp][1]);
                acc[rp][2] = ffma2(ap[rp], wd[2], acc[rp][2]);
                acc[rp][3] = ffma2(ap[rp], wd[3], acc[rp][3]);
            }
        }
    }
}

__device__ __forceinline__ void add_bias(float2 acc[8][4], const float4* b4, int tc) {
    float4 b = b4[tc];
    float bb[4] = { b.x, b.y, b.z, b.w };
#pragma unroll
    for (int rp = 0; rp < 8; rp++)
#pragma unroll
        for (int c = 0; c < 4; c++) { acc[rp][c].x += bb[c]; acc[rp][c].y += bb[c]; }
}

__global__ void __launch_bounds__(128)
edge_kernel(const int*   __restrict__ pe_index, const float* __restrict__ pe_val,
            const float* __restrict__ W_in, const float* __restrict__ b_in,
            const float* __restrict__ W1,   const float* __restrict__ b1,
            const float* __restrict__ W2,   const float* __restrict__ b2,
            const float* __restrict__ Wf,   const float* __restrict__ bf,
            const float4* __restrict__ xh4,
            float* __restrict__ wV, float* __restrict__ deg)
{
    __shared__ float4 sG[HID * 16];   // 32 KB swizzled activation buffer [k][64 rows]
    __shared__ float4 sW[16 * 32];    // 8 KB weight chunk (16 K-rows x 128 cols)
    __shared__ int    sIdx[2 * TILE];

    int tid = threadIdx.x;
    int tr  = tid >> 5;        // 0..3
    int tc  = tid & 31;        // 0..31
    int c0  = tc * 4;
    int e0  = blockIdx.x * TILE;

    // ---- load pe tile (transpose + swizzle into sG, k<24) and indices ----
    float* sGf = (float*)sG;
#pragma unroll
    for (int t = 0; t < 12; t++) {
        int idx = t * 128 + tid;           // 0..1535
        float v = pe_val[(size_t)e0 * 24 + idx];
        int r = idx / 24, k = idx - r * 24;
        sGf[aidx(k, r >> 2) * 4 + (r & 3)] = v;
    }
    if (tid < TILE) {
        sIdx[tid]        = pe_index[e0 + tid];        // tgt
        sIdx[TILE + tid] = pe_index[NE + e0 + tid];   // src
    }
    // gemm_stage's internal double __syncthreads orders these writes vs reads.

    float2 acc[8][4];
    float2 x0 [8][4];

    // ---- stage 1: x0 = pe @ W_in + b_in  (K=24) ----
    gemm_stage(acc, (const float4*)W_in, 24, sG, sW, tid, tr, tc);
    add_bias(acc, (const float4*)b_in, tc);
#pragma unroll
    for (int rp = 0; rp < 8; rp++)
#pragma unroll
        for (int c = 0; c < 4; c++) x0[rp][c] = acc[rp][c];
    __syncthreads();   // all reads of sG(pe) done before overwrite
#pragma unroll
    for (int c = 0; c < 4; c++)
#pragma unroll
        for (int j = 0; j < 4; j++)
            sG[aidx(c0 + c, tr * 4 + j)] = make_float4(
                gelu_f(acc[2*j][c].x),   gelu_f(acc[2*j][c].y),
                gelu_f(acc[2*j+1][c].x), gelu_f(acc[2*j+1][c].y));

    // ---- stage 2: h = gelu(x0) @ W1 + b1 ----
    gemm_stage(acc, (const float4*)W1, HID, sG, sW, tid, tr, tc);
    add_bias(acc, (const float4*)b1, tc);
    __syncthreads();
#pragma unroll
    for (int c = 0; c < 4; c++)
#pragma unroll
        for (int j = 0; j < 4; j++)
            sG[aidx(c0 + c, tr * 4 + j)] = make_float4(
                gelu_f(acc[2*j][c].x),   gelu_f(acc[2*j][c].y),
                gelu_f(acc[2*j+1][c].x), gelu_f(acc[2*j+1][c].y));

    // ---- stage 3: h2 = gelu(h) @ W2 + b2 ; res = h2 + x0 ----
    gemm_stage(acc, (const float4*)W2, HID, sG, sW, tid, tr, tc);
    add_bias(acc, (const float4*)b2, tc);
#pragma unroll
    for (int rp = 0; rp < 8; rp++)
#pragma unroll
        for (int c = 0; c < 4; c++) {
            acc[rp][c].x += x0[rp][c].x;
            acc[rp][c].y += x0[rp][c].y;
        }
    __syncthreads();
#pragma unroll
    for (int c = 0; c < 4; c++)
#pragma unroll
        for (int j = 0; j < 4; j++)
            sG[aidx(c0 + c, tr * 4 + j)] = make_float4(
                acc[2*j][c].x,   acc[2*j][c].y,
                acc[2*j+1][c].x, acc[2*j+1][c].y);

    // ---- stage 4: score = res @ W_fin + b_fin ----
    gemm_stage(acc, (const float4*)Wf, HID, sG, sW, tid, tr, tc);
    add_bias(acc, (const float4*)bf, tc);

    // ---- message: msg = xh[src]*score, scatter-add to wV[tgt], deg[tgt]++ ----
    int r0 = tr * 16;
#pragma unroll
    for (int rp = 0; rp < 8; rp++) {
#pragma unroll
        for (int h2 = 0; h2 < 2; h2++) {
            int rr   = rp * 2 + h2;
            int tgt  = sIdx[r0 + rr];
            int srcn = sIdx[TILE + r0 + rr];
            float4 xv = xh4[(size_t)srcn * 32 + tc];
            float s0 = h2 ? acc[rp][0].y : acc[rp][0].x;
            float s1 = h2 ? acc[rp][1].y : acc[rp][1].x;
            float s2 = h2 ? acc[rp][2].y : acc[rp][2].x;
            float s3 = h2 ? acc[rp][3].y : acc[rp][3].x;
            float* wrow = wV + (size_t)tgt * 128 + c0;
            atomicAdd(wrow + 0, xv.x * s0);
            atomicAdd(wrow + 1, xv.y * s1);
            atomicAdd(wrow + 2, xv.z * s2);
            atomicAdd(wrow + 3, xv.w * s3);
            if (tc == 0) atomicAdd(deg + tgt, 1.0f);
        }
    }
}

// ---------------- node projection: xh = x @ W_x + b_x ----------------
__global__ void __launch_bounds__(256)
xh_kernel(const float* __restrict__ x, const float* __restrict__ Wx,
          const float* __restrict__ bx, float* __restrict__ xh)
{
    __shared__ float sx[2][64];
    int tid = threadIdx.x;
    int n0  = blockIdx.x * 2;
    if (tid < 128) sx[tid >> 6][tid & 63] = x[(size_t)(n0 + (tid >> 6)) * 64 + (tid & 63)];
    __syncthreads();
    int ln = tid >> 7;        // node within block
    int c  = tid & 127;
    float s = bx[c];
#pragma unroll 4
    for (int k = 0; k < 64; k++)
        s += sx[ln][k] * Wx[k * 128 + c];
    xh[(size_t)(n0 + ln) * 128 + c] = s;
}

// ---------------- output projection ----------------
__global__ void __launch_bounds__(256)
out_kernel(const float* __restrict__ wV, const float* __restrict__ deg,
           const float* __restrict__ hb, const float* __restrict__ Wout,
           const float* __restrict__ bout, float* __restrict__ out)
{
    __shared__ float sh[4][128];
    int tid = threadIdx.x;
    int n0  = blockIdx.x * 4;
#pragma unroll
    for (int i = tid; i < 512; i += 256) {
        int nn = i >> 7, k = i & 127;
        int n  = n0 + nn;
        float d = deg[n];
        float invd = 1.0f / (d > 1.0f ? d : 1.0f);
        sh[nn][k] = wV[(size_t)n * 128 + k] * invd + hb[k];
    }
    __syncthreads();
    int nn = tid >> 6, c = tid & 63;
    float s = bout[c];
#pragma unroll 4
    for (int k = 0; k < 128; k++)
        s += sh[nn][k] * Wout[k * 64 + c];
    out[(size_t)(n0 + nn) * 64 + c] = s;
}

// ---------------- launch ----------------
extern "C" void kernel_launch(void* const* d_in, const int* in_sizes, int n_in,
                              void* d_out, int out_size)
{
    const float* x        = (const float*)d_in[0];
    const int*   pe_index = (const int*)  d_in[1];
    const float* pe_val   = (const float*)d_in[2];
    const float* W_in     = (const float*)d_in[3];
    const float* b_in     = (const float*)d_in[4];
    const float* W1       = (const float*)d_in[5];
    const float* b1       = (const float*)d_in[6];
    const float* W2       = (const float*)d_in[7];
    const float* b2       = (const float*)d_in[8];
    const float* W_fin    = (const float*)d_in[9];
    const float* b_fin    = (const float*)d_in[10];
    const float* W_x      = (const float*)d_in[11];
    const float* b_x      = (const float*)d_in[12];
    const float* head_b   = (const float*)d_in[13];
    const float* W_out    = (const float*)d_in[14];
    const float* b_out    = (const float*)d_in[15];
    float* out = (float*)d_out;

    void *p_xh, *p_wV, *p_deg;
    cudaGetSymbolAddress(&p_xh,  g_xh4);
    cudaGetSymbolAddress(&p_wV,  g_wV);
    cudaGetSymbolAddress(&p_deg, g_deg);

    cudaMemsetAsync(p_wV,  0, (size_t)NN * 128 * sizeof(float));
    cudaMemsetAsync(p_deg, 0, (size_t)NN * sizeof(float));

    xh_kernel<<<NN / 2, 256>>>(x, W_x, b_x, (float*)p_xh);

    edge_kernel<<<NE / TILE, 128>>>(pe_index, pe_val,
                                    W_in, b_in, W1, b1, W2, b2, W_fin, b_fin,
                                    (const float4*)p_xh, (float*)p_wV, (float*)p_deg);

    out_kernel<<<NN / 4, 256>>>((const float*)p_wV, (const float*)p_deg,
                                head_b, W_out, b_out, out);
}

// round 2
// speedup vs baseline: 1.3288x; 1.3288x over previous
#include <cuda_runtime.h>
#include <cuda_bf16.h>
#include <math.h>

#define NE    800000
#define NN    50000
#define TILE  64
#define HID   128

// ---------------- scratch (static device globals; no allocation) ----------------
__device__ float4 g_xh4[NN * 32];       // xh = x@W_x + b_x, [N,128] as float4
__device__ float  g_wV [NN * 128];      // scatter-add accumulator
__device__ float  g_deg[NN];            // degree accumulator

// ---------------- helpers ----------------
union U2 { float2 f; unsigned long long u; };

__device__ __forceinline__ float2 ffma2(float2 a, float2 b, float2 c) {
    U2 A, B, C, D; A.f = a; B.f = b; C.f = c;
    asm("fma.rn.f32x2 %0, %1, %2, %3;" : "=l"(D.u) : "l"(A.u), "l"(B.u), "l"(C.u));
    return D.f;
}

// swizzled activation buffer index (float4 quads): k in [0,128), rq in [0,16)
__device__ __forceinline__ int aidx(int k, int rq) {
    return (k << 4) + (rq ^ ((k >> 2) & 7));
}

__device__ __forceinline__ float gelu_f(float x) {
    return 0.5f * x * (1.0f + erff(x * 0.70710678118654752f));
}

__device__ __forceinline__ void red4(float* p, float a, float b, float c, float d) {
    asm volatile("red.global.add.v4.f32 [%0], {%1, %2, %3, %4};"
                 :: "l"(p), "f"(a), "f"(b), "f"(c), "f"(d) : "memory");
}

// ---------------- fused edge kernel ----------------
// 128 threads: tr = tid>>5 (row group, 16 edges), tc = tid&31.
// Each thread: acc[8][4] packed float2 over row pairs = 16 rows x 4 consecutive
// cols (4*tc .. 4*tc+3).
// sW2: double-buffered duplicated weights: logical col c=4q+j of row kk lives at
// sW2[buf][kk*128 + j*32 + q] as {w,w}. Load for thread tc, col-j: [kk*128+j*32+tc]
// -> 8B-stride conflict-free LDS.64, zero packing MOVs.
__device__ __forceinline__ void gemm_stage(
    float2 acc[8][4], const float4* __restrict__ Wg, int Kc, int Kw,
    const float4* sG, float2* sW2, int tid, int tr, int tc)
{
#pragma unroll
    for (int rp = 0; rp < 8; rp++)
#pragma unroll
        for (int c = 0; c < 4; c++) acc[rp][c] = make_float2(0.f, 0.f);

    int nch = Kc >> 4;

    // prefetch chunk 0 into registers
    float4 pf[4];
#pragma unroll
    for (int i = 0; i < 4; i++) {
        int idx = tid + i * 128;
        int kk  = idx >> 5;
        pf[i] = (kk < Kw) ? Wg[idx] : make_float4(0.f, 0.f, 0.f, 0.f);
    }

    for (int ch = 0; ch < nch; ch++) {
        float2* sWb = sW2 + (ch & 1) * 2048;
        // store duplicated weights (permuted layout)
#pragma unroll
        for (int i = 0; i < 4; i++) {
            int idx = tid + i * 128;
            int kk  = idx >> 5;
            int cg  = idx & 31;
            float2* p = sWb + kk * 128 + cg;
            p[0]  = make_float2(pf[i].x, pf[i].x);
            p[32] = make_float2(pf[i].y, pf[i].y);
            p[64] = make_float2(pf[i].z, pf[i].z);
            p[96] = make_float2(pf[i].w, pf[i].w);
        }
        __syncthreads();

        // prefetch next chunk (latency hidden under compute)
        if (ch + 1 < nch) {
            int k0n = (ch + 1) * 16;
#pragma unroll
            for (int i = 0; i < 4; i++) {
                int idx = tid + i * 128;
                int kk  = k0n + (idx >> 5);
                pf[i] = (kk < Kw) ? Wg[k0n * 32 + idx] : make_float4(0.f, 0.f, 0.f, 0.f);
            }
        }

        int k0 = ch * 16;
#pragma unroll
        for (int kk = 0; kk < 16; kk++) {
            int k = k0 + kk;
            float2 wd0 = sWb[kk * 128 +       tc];
            float2 wd1 = sWb[kk * 128 +  32 + tc];
            float2 wd2 = sWb[kk * 128 +  64 + tc];
            float2 wd3 = sWb[kk * 128 +  96 + tc];
            float4 a0 = sG[aidx(k, tr * 4 + 0)];
            float4 a1 = sG[aidx(k, tr * 4 + 1)];
            float4 a2 = sG[aidx(k, tr * 4 + 2)];
            float4 a3 = sG[aidx(k, tr * 4 + 3)];
            float2 ap[8] = { {a0.x,a0.y},{a0.z,a0.w},{a1.x,a1.y},{a1.z,a1.w},
                             {a2.x,a2.y},{a2.z,a2.w},{a3.x,a3.y},{a3.z,a3.w} };
#pragma unroll
            for (int rp = 0; rp < 8; rp++) {
                acc[rp][0] = ffma2(ap[rp], wd0, acc[rp][0]);
                acc[rp][1] = ffma2(ap[rp], wd1, acc[rp][1]);
                acc[rp][2] = ffma2(ap[rp], wd2, acc[rp][2]);
                acc[rp][3] = ffma2(ap[rp], wd3, acc[rp][3]);
            }
        }
        // no trailing sync: next iteration's pre-store sync provides WAR safety
        // (readers of buf finished before the sync one iteration ago)
        if (ch + 1 < nch) __syncthreads();
    }
}

__device__ __forceinline__ void add_bias(float2 acc[8][4], const float4* b4, int tc) {
    float4 b = b4[tc];
    float bb[4] = { b.x, b.y, b.z, b.w };
#pragma unroll
    for (int rp = 0; rp < 8; rp++)
#pragma unroll
        for (int c = 0; c < 4; c++) { acc[rp][c].x += bb[c]; acc[rp][c].y += bb[c]; }
}

__global__ void __launch_bounds__(128)
edge_kernel(const int*   __restrict__ pe_index, const float* __restrict__ pe_val,
            const float* __restrict__ W_in, const float* __restrict__ b_in,
            const float* __restrict__ W1,   const float* __restrict__ b1,
            const float* __restrict__ W2,   const float* __restrict__ b2,
            const float* __restrict__ Wf,   const float* __restrict__ bf,
            const float4* __restrict__ xh4,
            float* __restrict__ wV, float* __restrict__ deg)
{
    extern __shared__ char smem[];
    float4* sG   = (float4*)smem;                  // 32 KB activations [k][16 rq] swizzled
    float2* sW2  = (float2*)(smem + 32768);        // 32 KB double-buffered dup weights
    int*    sIdx = (int*)   (smem + 65536);        // 512 B indices

    int tid = threadIdx.x;
    int tr  = tid >> 5;        // 0..3
    int tc  = tid & 31;        // 0..31
    int c0  = tc * 4;
    int e0  = blockIdx.x * TILE;

    // ---- load pe tile (transpose + swizzle into sG, k<24) and indices ----
    float* sGf = (float*)sG;
#pragma unroll
    for (int t = 0; t < 12; t++) {
        int idx = t * 128 + tid;           // 0..1535
        float v = pe_val[(size_t)e0 * 24 + idx];
        int r = idx / 24, k = idx - r * 24;
        sGf[aidx(k, r >> 2) * 4 + (r & 3)] = v;
    }
    // zero-pad k = 24..31 (stage-1 compute runs Kc=32 with zero weights+acts)
    sG[aidx(24 + (tid >> 4), tid & 15)] = make_float4(0.f, 0.f, 0.f, 0.f);
    if (tid < TILE) {
        sIdx[tid]        = pe_index[e0 + tid];        // tgt
        sIdx[TILE + tid] = pe_index[NE + e0 + tid];   // src
    }
    // gemm_stage's internal sync (after sW store) orders these writes vs reads.

    float2 acc[8][4];
    float2 x0 [8][4];

    // ---- stage 1: x0 = pe @ W_in + b_in  (K=24, padded to 32) ----
    gemm_stage(acc, (const float4*)W_in, 32, 24, sG, sW2, tid, tr, tc);
    add_bias(acc, (const float4*)b_in, tc);
#pragma unroll
    for (int rp = 0; rp < 8; rp++)
#pragma unroll
        for (int c = 0; c < 4; c++) x0[rp][c] = acc[rp][c];
    __syncthreads();   // all reads of sG(pe) done before overwrite
#pragma unroll
    for (int c = 0; c < 4; c++)
#pragma unroll
        for (int j = 0; j < 4; j++)
            sG[aidx(c0 + c, tr * 4 + j)] = make_float4(
                gelu_f(acc[2*j][c].x),   gelu_f(acc[2*j][c].y),
                gelu_f(acc[2*j+1][c].x), gelu_f(acc[2*j+1][c].y));

    // ---- stage 2: h = gelu(x0) @ W1 + b1 ----
    gemm_stage(acc, (const float4*)W1, HID, HID, sG, sW2, tid, tr, tc);
    add_bias(acc, (const float4*)b1, tc);
    __syncthreads();
#pragma unroll
    for (int c = 0; c < 4; c++)
#pragma unroll
        for (int j = 0; j < 4; j++)
            sG[aidx(c0 + c, tr * 4 + j)] = make_float4(
                gelu_f(acc[2*j][c].x),   gelu_f(acc[2*j][c].y),
                gelu_f(acc[2*j+1][c].x), gelu_f(acc[2*j+1][c].y));

    // ---- stage 3: h2 = gelu(h) @ W2 + b2 ; res = h2 + x0 ----
    gemm_stage(acc, (const float4*)W2, HID, HID, sG, sW2, tid, tr, tc);
    add_bias(acc, (const float4*)b2, tc);
#pragma unroll
    for (int rp = 0; rp < 8; rp++)
#pragma unroll
        for (int c = 0; c < 4; c++) {
            acc[rp][c].x += x0[rp][c].x;
            acc[rp][c].y += x0[rp][c].y;
        }
    __syncthreads();
#pragma unroll
    for (int c = 0; c < 4; c++)
#pragma unroll
        for (int j = 0; j < 4; j++)
            sG[aidx(c0 + c, tr * 4 + j)] = make_float4(
                acc[2*j][c].x,   acc[2*j][c].y,
                acc[2*j+1][c].x, acc[2*j+1][c].y);

    // ---- stage 4: score = res @ W_fin + b_fin ----
    gemm_stage(acc, (const float4*)Wf, HID, HID, sG, sW2, tid, tr, tc);
    add_bias(acc, (const float4*)bf, tc);

    // ---- message: msg = xh[src]*score, scatter-add to wV[tgt], deg[tgt]++ ----
    int r0 = tr * 16;
#pragma unroll
    for (int rp = 0; rp < 8; rp++) {
#pragma unroll
        for (int h2 = 0; h2 < 2; h2++) {
            int rr   = rp * 2 + h2;
            int tgt  = sIdx[r0 + rr];
            int srcn = sIdx[TILE + r0 + rr];
            float4 xv = xh4[(size_t)srcn * 32 + tc];
            float v0 = xv.x * (h2 ? acc[rp][0].y : acc[rp][0].x);
            float v1 = xv.y * (h2 ? acc[rp][1].y : acc[rp][1].x);
            float v2 = xv.z * (h2 ? acc[rp][2].y : acc[rp][2].x);
            float v3 = xv.w * (h2 ? acc[rp][3].y : acc[rp][3].x);
            red4(wV + (size_t)tgt * 128 + c0, v0, v1, v2, v3);
            if (tc == 0) atomicAdd(deg + tgt, 1.0f);
        }
    }
}

// ---------------- node projection: xh = x @ W_x + b_x (4 nodes/block) ----------------
__global__ void __launch_bounds__(128)
xh_kernel(const float* __restrict__ x, const float* __restrict__ Wx,
          const float* __restrict__ bx, float* __restrict__ xh)
{
    __shared__ float sx[4][64];
    int tid = threadIdx.x;
    int n0  = blockIdx.x * 4;
#pragma unroll
    for (int i = tid; i < 256; i += 128)
        sx[i >> 6][i & 63] = x[(size_t)n0 * 64 + i];
    __syncthreads();
    int c = tid;               // 0..127
    float s0 = bx[c], s1 = s0, s2 = s0, s3 = s0;
#pragma unroll 8
    for (int k = 0; k < 64; k++) {
        float w = Wx[k * 128 + c];
        s0 += sx[0][k] * w;
        s1 += sx[1][k] * w;
        s2 += sx[2][k] * w;
        s3 += sx[3][k] * w;
    }
    xh[(size_t)(n0 + 0) * 128 + c] = s0;
    xh[(size_t)(n0 + 1) * 128 + c] = s1;
    xh[(size_t)(n0 + 2) * 128 + c] = s2;
    xh[(size_t)(n0 + 3) * 128 + c] = s3;
}

// ---------------- output projection (8 nodes/block, 2 nodes/thread) ----------------
__global__ void __launch_bounds__(256)
out_kernel(const float* __restrict__ wV, const float* __restrict__ deg,
           const float* __restrict__ hb, const float* __restrict__ Wout,
           const float* __restrict__ bout, float* __restrict__ out)
{
    __shared__ float sh[8][128];
    int tid = threadIdx.x;
    int n0  = blockIdx.x * 8;
#pragma unroll
    for (int i = tid; i < 1024; i += 256) {
        int nn = i >> 7, k = i & 127;
        int n  = n0 + nn;
        float d = deg[n];
        float invd = 1.0f / (d > 1.0f ? d : 1.0f);
        sh[nn][k] = wV[(size_t)n * 128 + k] * invd + hb[k];
    }
    __syncthreads();
    int g = tid >> 6, c = tid & 63;
    float s0 = bout[c], s1 = s0;
#pragma unroll 8
    for (int k = 0; k < 128; k++) {
        float w = Wout[k * 64 + c];
        s0 += sh[2 * g + 0][k] * w;
        s1 += sh[2 * g + 1][k] * w;
    }
    out[(size_t)(n0 + 2 * g + 0) * 64 + c] = s0;
    out[(size_t)(n0 + 2 * g + 1) * 64 + c] = s1;
}

// ---------------- launch ----------------
extern "C" void kernel_launch(void* const* d_in, const int* in_sizes, int n_in,
                              void* d_out, int out_size)
{
    const float* x        = (const float*)d_in[0];
    const int*   pe_index = (const int*)  d_in[1];
    const float* pe_val   = (const float*)d_in[2];
    const float* W_in     = (const float*)d_in[3];
    const float* b_in     = (const float*)d_in[4];
    const float* W1       = (const float*)d_in[5];
    const float* b1       = (const float*)d_in[6];
    const float* W2       = (const float*)d_in[7];
    const float* b2       = (const float*)d_in[8];
    const float* W_fin    = (const float*)d_in[9];
    const float* b_fin    = (const float*)d_in[10];
    const float* W_x      = (const float*)d_in[11];
    const float* b_x      = (const float*)d_in[12];
    const float* head_b   = (const float*)d_in[13];
    const float* W_out    = (const float*)d_in[14];
    const float* b_out    = (const float*)d_in[15];
    float* out = (float*)d_out;

    void *p_xh, *p_wV, *p_deg;
    cudaGetSymbolAddress(&p_xh,  g_xh4);
    cudaGetSymbolAddress(&p_wV,  g_wV);
    cudaGetSymbolAddress(&p_deg, g_deg);

    const int EDGE_SMEM = 32768 + 32768 + 512;
    cudaFuncSetAttribute(edge_kernel, cudaFuncAttributeMaxDynamicSharedMemorySize,
                         EDGE_SMEM);

    cudaMemsetAsync(p_wV,  0, (size_t)NN * 128 * sizeof(float));
    cudaMemsetAsync(p_deg, 0, (size_t)NN * sizeof(float));

    xh_kernel<<<NN / 4, 128>>>(x, W_x, b_x, (float*)p_xh);

    edge_kernel<<<NE / TILE, 128, EDGE_SMEM>>>(pe_index, pe_val,
                                    W_in, b_in, W1, b1, W2, b2, W_fin, b_fin,
                                    (const float4*)p_xh, (float*)p_wV, (float*)p_deg);

    out_kernel<<<NN / 8, 256>>>((const float*)p_wV, (const float*)p_deg,
                                head_b, W_out, b_out, out);
}

// round 4
// speedup vs baseline: 3.3298x; 2.5060x over previous
#include <cuda_runtime.h>
#include <math.h>
#include <stdint.h>

#define NE  800000
#define NN  50000
#define HID 128

// ---------------- scratch (static device globals; no allocation) ----------------
__device__ float4   g_xh4[NN * 32];     // xh = x@W_x + b_x, [N,128] as float4
__device__ float    g_wV [NN * 128];    // scatter-add accumulator
__device__ float    g_deg[NN];          // degree accumulator
// fragment-linear tf32 B operands: uint2 {b0,b1} per (ntile, kstep, lane)
__device__ uint2    g_fWin[16 * 4  * 32];   // 16 KB  (K padded to 32, zeros past 24)
__device__ uint2    g_fW1 [16 * 16 * 32];   // 64 KB
__device__ uint2    g_fW2 [16 * 16 * 32];   // 64 KB
__device__ uint2    g_fWf [16 * 16 * 32];   // 64 KB

// ---------------- SMEM layout (edge kernel, dynamic) ----------------
#define OFF_A    0          // 64KB A tile: 128 rows x 128 tf32, 16B-XOR swizzled
#define OFF_B0   65536      // 64KB frag buffer 0
#define OFF_B1   131072     // 64KB frag buffer 1
#define OFF_WIN  196608     // 16KB Win frag buffer
#define OFF_BIAS 212992     // 2KB: 4 stages x 128 floats
#define OFF_IDX  215040     // 1KB: tgt[128], src[128]
#define SMEM_TOT 216064

// ---------------- helpers ----------------
__device__ __forceinline__ uint32_t f2tf32(float f) {
    uint32_t r; asm("cvt.rna.tf32.f32 %0, %1;" : "=r"(r) : "f"(f)); return r;
}
__device__ __forceinline__ float gelu_f(float x) {
    return 0.5f * x * (1.0f + erff(x * 0.70710678118654752f));
}
__device__ __forceinline__ void red4(float* p, float a, float b, float c, float d) {
    asm volatile("red.global.add.v4.f32 [%0], {%1,%2,%3,%4};"
                 :: "l"(p), "f"(a), "f"(b), "f"(c), "f"(d) : "memory");
}
__device__ __forceinline__ uint32_t s2u(const void* p) {
    uint32_t a;
    asm("{ .reg .u64 t; cvta.to.shared.u64 t, %1; cvt.u32.u64 %0, t; }" : "=r"(a) : "l"(p));
    return a;
}
__device__ __forceinline__ void cp16(uint32_t s, const void* g) {
    asm volatile("cp.async.cg.shared.global [%0], [%1], 16;" :: "r"(s), "l"(g));
}
#define CP_COMMIT() asm volatile("cp.async.commit_group;")
#define CP_WAIT(n)  asm volatile("cp.async.wait_group %0;" :: "n"(n) : "memory")

__device__ __forceinline__ void mma8(float d[4], const uint32_t a[4], uint2 b) {
    asm volatile(
        "mma.sync.aligned.m16n8k8.row.col.f32.tf32.tf32.f32 "
        "{%0,%1,%2,%3},{%4,%5,%6,%7},{%8,%9},{%0,%1,%2,%3};"
        : "+f"(d[0]), "+f"(d[1]), "+f"(d[2]), "+f"(d[3])
        : "r"(a[0]), "r"(a[1]), "r"(a[2]), "r"(a[3]), "r"(b.x), "r"(b.y));
}

// ---------------- weight prep: fragment-linear tf32 B arrays ----------------
// For stage "act @ W" (W row-major [k][n]), mma B frag (k8 x n8, col-major):
//   b0 = W[(ks*8 + (lane&3))*128 + nt*8 + (lane>>2)], b1 = same with k+4.
__global__ void __launch_bounds__(256)
prep_kernel(const float* __restrict__ W_in, const float* __restrict__ W1,
            const float* __restrict__ W2,   const float* __restrict__ Wf)
{
    int idx = blockIdx.x * 256 + threadIdx.x;
    if (idx < 2048) {                      // Win: KS=4, Kreal=24
        int lane = idx & 31, ks = (idx >> 5) & 3, nt = idx >> 7;
        int k0 = ks * 8 + (lane & 3), n = nt * 8 + (lane >> 2);
        uint2 u;
        u.x = (k0     < 24) ? f2tf32(W_in[k0 * 128 + n])       : 0u;
        u.y = (k0 + 4 < 24) ? f2tf32(W_in[(k0 + 4) * 128 + n]) : 0u;
        g_fWin[idx] = u;
    } else {
        int r = idx - 2048;
        if (r >= 3 * 8192) return;
        int sel = r >> 13; r &= 8191;
        int lane = r & 31, ks = (r >> 5) & 15, nt = r >> 9;
        int k0 = ks * 8 + (lane & 3), n = nt * 8 + (lane >> 2);
        const float* W = (sel == 0) ? W1 : (sel == 1) ? W2 : Wf;
        uint2* F       = (sel == 0) ? g_fW1 : (sel == 1) ? g_fW2 : g_fWf;
        uint2 u;
        u.x = f2tf32(W[k0 * 128 + n]);
        u.y = f2tf32(W[(k0 + 4) * 128 + n]);
        F[r] = u;
    }
}

// ---------------- MMA stage: warp tile m32 x n64, K = KS*8 ----------------
// A in SMEM words: word(r,c) = r*128 + (((c>>2) ^ (r&7))<<2) + (c&3); row low-3-bits == g.
template<int KS>
__device__ __forceinline__ void mma_stage(
    float acc[2][8][4], const uint32_t* A32, const uint2* F,
    int mbase, int nc, int g, int t, int lane)
{
#pragma unroll
    for (int ks = 0; ks < KS; ks++) {
        uint32_t a[2][4];
#pragma unroll
        for (int mt = 0; mt < 2; mt++) {
            const uint32_t* base = A32 + (mbase + mt * 16 + g) * 128 + t;
            int sw0 = ((2 * ks)     ^ g) << 2;
            int sw1 = ((2 * ks + 1) ^ g) << 2;
            a[mt][0] = base[sw0];
            a[mt][1] = base[8 * 128 + sw0];
            a[mt][2] = base[sw1];
            a[mt][3] = base[8 * 128 + sw1];
        }
#pragma unroll
        for (int nt = 0; nt < 8; nt++) {
            uint2 b = F[((nc * 8 + nt) * KS + ks) * 32 + lane];
            mma8(acc[0][nt], a[0], b);
            mma8(acc[1][nt], a[1], b);
        }
    }
}

// MODE 0: gelu -> tf32 store; MODE 1: plain tf32 store; MODE 2: fp32 store
template<int MODE>
__device__ __forceinline__ void epilogue(
    float acc[2][8][4], const float* bias, uint32_t* A32,
    int mbase, int nbase, int g, int t)
{
#pragma unroll
    for (int nt = 0; nt < 8; nt++) {
        int c = nbase + nt * 8 + 2 * t;
        float2 bb = *(const float2*)(bias + c);
        int w = (((c >> 2) ^ g) << 2) + (c & 3);
#pragma unroll
        for (int mt = 0; mt < 2; mt++) {
            float v0 = acc[mt][nt][0] + bb.x, v1 = acc[mt][nt][1] + bb.y;
            float v2 = acc[mt][nt][2] + bb.x, v3 = acc[mt][nt][3] + bb.y;
            if (MODE == 0) {
                v0 = gelu_f(v0); v1 = gelu_f(v1);
                v2 = gelu_f(v2); v3 = gelu_f(v3);
            }
            int r0 = mbase + mt * 16 + g;
            if (MODE <= 1) {
                uint2 u0 = make_uint2(f2tf32(v0), f2tf32(v1));
                uint2 u1 = make_uint2(f2tf32(v2), f2tf32(v3));
                *(uint2*)(A32 + r0 * 128 + w)       = u0;
                *(uint2*)(A32 + (r0 + 8) * 128 + w) = u1;
            } else {
                *(float2*)(A32 + r0 * 128 + w)       = make_float2(v0, v1);
                *(float2*)(A32 + (r0 + 8) * 128 + w) = make_float2(v2, v3);
            }
        }
    }
}

// ---------------- fused edge kernel (mma.sync tf32) ----------------
__global__ void __launch_bounds__(256, 1)
edge_kernel(const int* __restrict__ pe_index, const float* __restrict__ pe_val,
            const float* __restrict__ b_in, const float* __restrict__ b1,
            const float* __restrict__ b2,   const float* __restrict__ bf,
            const float4* __restrict__ xh4,
            float* __restrict__ wV, float* __restrict__ deg)
{
    extern __shared__ char smem[];
    uint32_t sm = s2u(smem);
    uint32_t* A32   = (uint32_t*)(smem + OFF_A);
    const uint2* F0 = (const uint2*)(smem + OFF_B0);
    const uint2* F1 = (const uint2*)(smem + OFF_B1);
    const uint2* FW = (const uint2*)(smem + OFF_WIN);
    float* sBias    = (float*)(smem + OFF_BIAS);
    int*   sIdx     = (int*)(smem + OFF_IDX);

    int tid  = threadIdx.x;
    int wid  = tid >> 5, lane = tid & 31;
    int mr   = wid & 3,  nc   = wid >> 2;
    int g    = lane >> 2, t   = lane & 3;
    int mbase = mr * 32, nbase = nc * 64;
    int e0   = blockIdx.x * 128;

    // --- stage frag buffers via cp.async ---
#pragma unroll
    for (int i = 0; i < 4; i++)
        cp16(sm + OFF_WIN + (i * 256 + tid) * 16, (const char*)g_fWin + (i * 256 + tid) * 16);
    CP_COMMIT();
#pragma unroll
    for (int i = 0; i < 16; i++)
        cp16(sm + OFF_B0 + (i * 256 + tid) * 16, (const char*)g_fW1 + (i * 256 + tid) * 16);
    CP_COMMIT();
#pragma unroll
    for (int i = 0; i < 16; i++)
        cp16(sm + OFF_B1 + (i * 256 + tid) * 16, (const char*)g_fW2 + (i * 256 + tid) * 16);
    CP_COMMIT();

    // --- indices + biases ---
    sIdx[tid] = (tid < 128) ? pe_index[e0 + tid] : pe_index[NE + e0 + (tid - 128)];
#pragma unroll
    for (int i = tid; i < 512; i += 256) {
        int st = i >> 7, c = i & 127;
        float v = (st == 0) ? b_in[c] : (st == 1) ? b1[c]
                : (st == 2) ? (b_in[c] + b2[c])   : bf[c];
        sBias[i] = v;
    }

    // --- build A from pe_val (tf32, K padded 24->32 with zeros) ---
    {
        int row = tid >> 1, half = tid & 1;
        const float* pr = pe_val + (size_t)(e0 + row) * 24;
        uint32_t* Arow = A32 + row * 128;
        int rs = row & 7;
#pragma unroll
        for (int q = 0; q < 4; q++) {
            int cb = half * 16 + q * 4;
            uint4 u = make_uint4(0u, 0u, 0u, 0u);
            if (cb < 24) {
                float4 v = *(const float4*)(pr + cb);
                u = make_uint4(f2tf32(v.x), f2tf32(v.y), f2tf32(v.z), f2tf32(v.w));
            }
            *(uint4*)(Arow + (((cb >> 2) ^ rs) << 2)) = u;
        }
    }

    float acc[2][8][4], x0[2][8][4];

    CP_WAIT(2);
    __syncthreads();

    // ---- stage 1: acc = pe @ Win (K=32) ----
#pragma unroll
    for (int mt = 0; mt < 2; mt++)
#pragma unroll
        for (int nt = 0; nt < 8; nt++)
#pragma unroll
            for (int i = 0; i < 4; i++) acc[mt][nt][i] = 0.f;
    mma_stage<4>(acc, A32, FW, mbase, nc, g, t, lane);
#pragma unroll
    for (int mt = 0; mt < 2; mt++)
#pragma unroll
        for (int nt = 0; nt < 8; nt++)
#pragma unroll
            for (int i = 0; i < 4; i++) x0[mt][nt][i] = acc[mt][nt][i];

    CP_WAIT(1);
    __syncthreads();
    epilogue<0>(acc, sBias, A32, mbase, nbase, g, t);       // A = gelu(x0+b_in)
    __syncthreads();

    // ---- stage 2: acc = A @ W1 ----
#pragma unroll
    for (int mt = 0; mt < 2; mt++)
#pragma unroll
        for (int nt = 0; nt < 8; nt++)
#pragma unroll
            for (int i = 0; i < 4; i++) acc[mt][nt][i] = 0.f;
    mma_stage<16>(acc, A32, F0, mbase, nc, g, t, lane);
    __syncthreads();                                         // B0 reads + A reads done

    // prefetch Wf into B0
#pragma unroll
    for (int i = 0; i < 16; i++)
        cp16(sm + OFF_B0 + (i * 256 + tid) * 16, (const char*)g_fWf + (i * 256 + tid) * 16);
    CP_COMMIT();

    epilogue<0>(acc, sBias + 128, A32, mbase, nbase, g, t);  // A = gelu(h+b1)
    CP_WAIT(1);
    __syncthreads();

    // ---- stage 3: acc = x0 + A @ W2  (residual in accumulator init) ----
    mma_stage<16>(x0, A32, F1, mbase, nc, g, t, lane);
    __syncthreads();
    epilogue<1>(x0, sBias + 256, A32, mbase, nbase, g, t);   // A = res = h2+b2+x0+b_in
    CP_WAIT(0);
    __syncthreads();

    // ---- stage 4: acc = A @ Wf ----
#pragma unroll
    for (int mt = 0; mt < 2; mt++)
#pragma unroll
        for (int nt = 0; nt < 8; nt++)
#pragma unroll
            for (int i = 0; i < 4; i++) acc[mt][nt][i] = 0.f;
    mma_stage<16>(acc, A32, F0, mbase, nc, g, t, lane);
    __syncthreads();
    epilogue<2>(acc, sBias + 384, A32, mbase, nbase, g, t);  // A = scores (fp32)
    __syncthreads();

    // ---- scatter: msg = xh[src]*score -> wV[tgt], deg[tgt]++ ----
    float* S = (float*)(smem + OFF_A);
#pragma unroll 4
    for (int i = 0; i < 16; i++) {
        int e    = wid * 16 + i;
        int tgt  = sIdx[e];
        int srcn = sIdx[128 + e];
        float4 xv = xh4[(size_t)srcn * 32 + lane];
        float4 s4 = *(const float4*)(S + e * 128 + ((lane ^ (e & 7)) << 2));
        red4(wV + (size_t)tgt * 128 + lane * 4,
             xv.x * s4.x, xv.y * s4.y, xv.z * s4.z, xv.w * s4.w);
        if (lane == 0) atomicAdd(deg + tgt, 1.0f);
    }
}

// ---------------- node projection: xh = x @ W_x + b_x (4 nodes/block) ----------------
__global__ void __launch_bounds__(128)
xh_kernel(const float* __restrict__ x, const float* __restrict__ Wx,
          const float* __restrict__ bx, float* __restrict__ xh)
{
    __shared__ float sx[4][64];
    int tid = threadIdx.x;
    int n0  = blockIdx.x * 4;
#pragma unroll
    for (int i = tid; i < 256; i += 128)
        sx[i >> 6][i & 63] = x[(size_t)n0 * 64 + i];
    __syncthreads();
    int c = tid;
    float s0 = bx[c], s1 = s0, s2 = s0, s3 = s0;
#pragma unroll 8
    for (int k = 0; k < 64; k++) {
        float w = Wx[k * 128 + c];
        s0 += sx[0][k] * w; s1 += sx[1][k] * w;
        s2 += sx[2][k] * w; s3 += sx[3][k] * w;
    }
    xh[(size_t)(n0+0)*128 + c] = s0; xh[(size_t)(n0+1)*128 + c] = s1;
    xh[(size_t)(n0+2)*128 + c] = s2; xh[(size_t)(n0+3)*128 + c] = s3;
}

// ---------------- output projection ----------------
__global__ void __launch_bounds__(256)
out_kernel(const float* __restrict__ wV, const float* __restrict__ deg,
           const float* __restrict__ hb, const float* __restrict__ Wout,
           const float* __restrict__ bout, float* __restrict__ out)
{
    __shared__ float sh[8][128];
    int tid = threadIdx.x;
    int n0  = blockIdx.x * 8;
#pragma unroll
    for (int i = tid; i < 1024; i += 256) {
        int nn = i >> 7, k = i & 127;
        int n  = n0 + nn;
        float d = deg[n];
        float invd = 1.0f / (d > 1.0f ? d : 1.0f);
        sh[nn][k] = wV[(size_t)n * 128 + k] * invd + hb[k];
    }
    __syncthreads();
    int gg = tid >> 6, c = tid & 63;
    float s0 = bout[c], s1 = s0;
#pragma unroll 8
    for (int k = 0; k < 128; k++) {
        float w = Wout[k * 64 + c];
        s0 += sh[2*gg+0][k] * w;
        s1 += sh[2*gg+1][k] * w;
    }
    out[(size_t)(n0 + 2*gg + 0) * 64 + c] = s0;
    out[(size_t)(n0 + 2*gg + 1) * 64 + c] = s1;
}

// ---------------- launch ----------------
extern "C" void kernel_launch(void* const* d_in, const int* in_sizes, int n_in,
                              void* d_out, int out_size)
{
    const float* x        = (const float*)d_in[0];
    const int*   pe_index = (const int*)  d_in[1];
    const float* pe_val   = (const float*)d_in[2];
    const float* W_in     = (const float*)d_in[3];
    const float* b_in     = (const float*)d_in[4];
    const float* W1       = (const float*)d_in[5];
    const float* b1       = (const float*)d_in[6];
    const float* W2       = (const float*)d_in[7];
    const float* b2       = (const float*)d_in[8];
    const float* W_fin    = (const float*)d_in[9];
    const float* b_fin    = (const float*)d_in[10];
    const float* W_x      = (const float*)d_in[11];
    const float* b_x      = (const float*)d_in[12];
    const float* head_b   = (const float*)d_in[13];
    const float* W_out    = (const float*)d_in[14];
    const float* b_out    = (const float*)d_in[15];
    float* out = (float*)d_out;

    void *p_xh, *p_wV, *p_deg;
    cudaGetSymbolAddress(&p_xh,  g_xh4);
    cudaGetSymbolAddress(&p_wV,  g_wV);
    cudaGetSymbolAddress(&p_deg, g_deg);

    cudaFuncSetAttribute(edge_kernel, cudaFuncAttributeMaxDynamicSharedMemorySize,
                         SMEM_TOT);

    cudaMemsetAsync(p_wV,  0, (size_t)NN * 128 * sizeof(float));
    cudaMemsetAsync(p_deg, 0, (size_t)NN * sizeof(float));

    prep_kernel<<<104, 256>>>(W_in, W1, W2, W_fin);
    xh_kernel<<<NN / 4, 128>>>(x, W_x, b_x, (float*)p_xh);

    edge_kernel<<<NE / 128, 256, SMEM_TOT>>>(pe_index, pe_val,
        b_in, b1, b2, b_fin,
        (const float4*)p_xh, (float*)p_wV, (float*)p_deg);

    out_kernel<<<NN / 8, 256>>>((const float*)p_wV, (const float*)p_deg,
                                head_b, W_out, b_out, out);
}

// round 5
// speedup vs baseline: 5.4769x; 1.6448x over previous
#include <cuda_runtime.h>
#include <cuda_fp16.h>
#include <math.h>
#include <stdint.h>

#define NE  800000
#define NN  50000
#define HID 128

// ---------------- scratch (static device globals; no allocation) ----------------
__device__ float4 g_xh4[NN * 32];     // xh = x@W_x + b_x, [N,128] as float4
__device__ float  g_wV [NN * 128];    // scatter-add accumulator
__device__ float  g_deg[NN];          // degree accumulator
// fragment-linear fp16 B operands: uint2 {b0,b1} per (ntile, kstep, lane)
__device__ uint2  g_fWin[16 * 2 * 32];    // 8 KB  (K padded to 32, zeros past 24)
__device__ uint2  g_fW1 [16 * 8 * 32];    // 32 KB
__device__ uint2  g_fW2 [16 * 8 * 32];    // 32 KB
__device__ uint2  g_fWf [16 * 8 * 32];    // 32 KB

// ---------------- SMEM layout (edge kernel, dynamic) ----------------
#define OFF_A    0          // 32KB A tile: 128 rows x 128 fp16, XOR-swizzled
#define OFF_PE   32768      // 8KB  pe tile: 128 rows x 32 fp16 (K padded)
#define OFF_B0   40960      // 32KB frag buffer 0
#define OFF_B1   73728      // 32KB frag buffer 1
#define OFF_BIAS 106496     // 2KB: 4 stages x 128 floats
#define OFF_IDX  108544     // 1KB: tgt[128], src[128]
#define SMEM_TOT 109568
// scores overlay: fp32 [128][128] over B0+B1 (64KB exactly)

// ---------------- helpers ----------------
__device__ __forceinline__ uint32_t packh2(float lo, float hi) {
    __half2 h = __floats2half2_rn(lo, hi);
    return *(uint32_t*)&h;
}
__device__ __forceinline__ float gelu_f(float x) {
    return 0.5f * x * (1.0f + erff(x * 0.70710678118654752f));
}
__device__ __forceinline__ void red4(float* p, float a, float b, float c, float d) {
    asm volatile("red.global.add.v4.f32 [%0], {%1,%2,%3,%4};"
                 :: "l"(p), "f"(a), "f"(b), "f"(c), "f"(d) : "memory");
}
__device__ __forceinline__ uint32_t s2u(const void* p) {
    uint32_t a;
    asm("{ .reg .u64 t; cvta.to.shared.u64 t, %1; cvt.u32.u64 %0, t; }" : "=r"(a) : "l"(p));
    return a;
}
__device__ __forceinline__ void cp16(uint32_t s, const void* g) {
    asm volatile("cp.async.cg.shared.global [%0], [%1], 16;" :: "r"(s), "l"(g));
}
#define CP_COMMIT() asm volatile("cp.async.commit_group;")
#define CP_WAIT(n)  asm volatile("cp.async.wait_group %0;" :: "n"(n) : "memory")

__device__ __forceinline__ void mma16(float d[4], const uint32_t a[4], uint2 b) {
    asm volatile(
        "mma.sync.aligned.m16n8k16.row.col.f32.f16.f16.f32 "
        "{%0,%1,%2,%3},{%4,%5,%6,%7},{%8,%9},{%0,%1,%2,%3};"
        : "+f"(d[0]), "+f"(d[1]), "+f"(d[2]), "+f"(d[3])
        : "r"(a[0]), "r"(a[1]), "r"(a[2]), "r"(a[3]), "r"(b.x), "r"(b.y));
}

// ---------------- weight prep: fragment-linear fp16 B arrays ----------------
// m16n8k16 B frag (k16 x n8 col-major): b0 = {W[k0][n], W[k0+1][n]},
// b1 = {W[k0+8][n], W[k0+9][n]} with k0 = ks*16 + 2*(lane&3), n = nt*8 + (lane>>2).
__global__ void __launch_bounds__(256)
prep_kernel(const float* __restrict__ W_in, const float* __restrict__ W1,
            const float* __restrict__ W2,   const float* __restrict__ Wf)
{
    int idx = blockIdx.x * 256 + threadIdx.x;
    if (idx < 1024) {                     // Win: 16nt x 2ks x 32lane
        int lane = idx & 31, ks = (idx >> 5) & 1, nt = idx >> 6;
        int k0 = ks * 16 + 2 * (lane & 3), n = nt * 8 + (lane >> 2);
        uint2 u;
        u.x = packh2(k0     < 24 ? W_in[k0 * 128 + n]       : 0.f,
                     k0 + 1 < 24 ? W_in[(k0 + 1) * 128 + n] : 0.f);
        u.y = packh2(k0 + 8 < 24 ? W_in[(k0 + 8) * 128 + n] : 0.f,
                     k0 + 9 < 24 ? W_in[(k0 + 9) * 128 + n] : 0.f);
        g_fWin[nt * 64 + ks * 32 + lane] = u;
    } else {
        int r = idx - 1024;
        if (r >= 3 * 4096) return;
        int sel = r >> 12; r &= 4095;
        int lane = r & 31, ks = (r >> 5) & 7, nt = r >> 8;
        int k0 = ks * 16 + 2 * (lane & 3), n = nt * 8 + (lane >> 2);
        const float* W = (sel == 0) ? W1 : (sel == 1) ? W2 : Wf;
        uint2* F       = (sel == 0) ? g_fW1 : (sel == 1) ? g_fW2 : g_fWf;
        uint2 u;
        u.x = packh2(W[k0 * 128 + n],       W[(k0 + 1) * 128 + n]);
        u.y = packh2(W[(k0 + 8) * 128 + n], W[(k0 + 9) * 128 + n]);
        F[r] = u;
    }
}

// A tile word layout (fp16, 64 uint32 words/row): word(r,c2) = r*64 + (((c2>>2)^(r&7))<<2) + (c2&3)
template<int KS>
__device__ __forceinline__ void mma_stageA(
    float acc[2][8][4], const uint32_t* A32, const uint2* F,
    int mbase, int nc, int g, int t, int lane)
{
#pragma unroll
    for (int ks = 0; ks < KS; ks++) {
        uint32_t a[2][4];
#pragma unroll
        for (int mt = 0; mt < 2; mt++) {
            const uint32_t* b = A32 + (mbase + mt * 16 + g) * 64 + t;
            int q0 = ((2 * ks)     ^ g) << 2;
            int q1 = ((2 * ks + 1) ^ g) << 2;
            a[mt][0] = b[q0];
            a[mt][1] = b[8 * 64 + q0];
            a[mt][2] = b[q1];
            a[mt][3] = b[8 * 64 + q1];
        }
#pragma unroll
        for (int nt = 0; nt < 8; nt++) {
            uint2 bb = F[((nc * 8 + nt) * KS + ks) * 32 + lane];
            mma16(acc[0][nt], a[0], bb);
            mma16(acc[1][nt], a[1], bb);
        }
    }
}

// PE tile (fp16, 16 words/row): word(r,c2) = r*16 + (((c2>>2)^((r>>1)&3))<<2) + (c2&3)
__device__ __forceinline__ void mma_stagePE(
    float acc[2][8][4], const uint32_t* PE32, const uint2* __restrict__ FWin,
    int mbase, int nc, int g, int t, int lane)
{
#pragma unroll
    for (int ks = 0; ks < 2; ks++) {
        uint32_t a[2][4];
#pragma unroll
        for (int mt = 0; mt < 2; mt++) {
            int r = mbase + mt * 16 + g;
            int sw = (r >> 1) & 3;
            const uint32_t* b = PE32 + r * 16 + t;
            int q0 = ((2 * ks)     ^ sw) << 2;
            int q1 = ((2 * ks + 1) ^ sw) << 2;
            a[mt][0] = b[q0];
            a[mt][1] = b[8 * 16 + q0];   // (r+8)>>1 & 3 == sw
            a[mt][2] = b[q1];
            a[mt][3] = b[8 * 16 + q1];
        }
#pragma unroll
        for (int nt = 0; nt < 8; nt++) {
            uint2 bb = __ldg(&FWin[((nc * 8 + nt) * 2 + ks) * 32 + lane]);
            mma16(acc[0][nt], a[0], bb);
            mma16(acc[1][nt], a[1], bb);
        }
    }
}

__device__ __forceinline__ void zero_acc(float acc[2][8][4]) {
#pragma unroll
    for (int mt = 0; mt < 2; mt++)
#pragma unroll
        for (int nt = 0; nt < 8; nt++)
#pragma unroll
            for (int i = 0; i < 4; i++) acc[mt][nt][i] = 0.f;
}

// MODE 0: gelu -> fp16 store to A; MODE 1: plain fp16 store to A
template<int MODE>
__device__ __forceinline__ void epilogueH(
    float acc[2][8][4], const float* bias, uint32_t* A32,
    int mbase, int nbase, int g, int t)
{
#pragma unroll
    for (int nt = 0; nt < 8; nt++) {
        int c = nbase + nt * 8 + 2 * t;
        float2 bb = *(const float2*)(bias + c);
        int c2 = c >> 1;
        int w  = (((c2 >> 2) ^ g) << 2) + (c2 & 3);
#pragma unroll
        for (int mt = 0; mt < 2; mt++) {
            int r0 = mbase + mt * 16 + g;
            float v0 = acc[mt][nt][0] + bb.x, v1 = acc[mt][nt][1] + bb.y;
            float v2 = acc[mt][nt][2] + bb.x, v3 = acc[mt][nt][3] + bb.y;
            if (MODE == 0) {
                v0 = gelu_f(v0); v1 = gelu_f(v1);
                v2 = gelu_f(v2); v3 = gelu_f(v3);
            }
            A32[r0 * 64 + w]       = packh2(v0, v1);
            A32[(r0 + 8) * 64 + w] = packh2(v2, v3);
        }
    }
}

// scores epilogue: fp32 into S with per-row 16B-chunk XOR swizzle
__device__ __forceinline__ void epilogueS(
    float acc[2][8][4], const float* bias, float* S,
    int mbase, int nbase, int g, int t)
{
#pragma unroll
    for (int nt = 0; nt < 8; nt++) {
        int c = nbase + nt * 8 + 2 * t;
        float2 bb = *(const float2*)(bias + c);
        int w = (((c >> 2) ^ g) << 2) + (c & 3);
#pragma unroll
        for (int mt = 0; mt < 2; mt++) {
            int r0 = mbase + mt * 16 + g;
            *(float2*)(S + r0 * 128 + w) =
                make_float2(acc[mt][nt][0] + bb.x, acc[mt][nt][1] + bb.y);
            *(float2*)(S + (r0 + 8) * 128 + w) =
                make_float2(acc[mt][nt][2] + bb.x, acc[mt][nt][3] + bb.y);
        }
    }
}

// ---------------- fused edge kernel (mma.sync fp16, 2 CTAs/SM) ----------------
__global__ void __launch_bounds__(256, 2)
edge_kernel(const int* __restrict__ pe_index, const float* __restrict__ pe_val,
            const float* __restrict__ b_in, const float* __restrict__ b1,
            const float* __restrict__ b2,   const float* __restrict__ bf,
            const float4* __restrict__ xh4,
            float* __restrict__ wV, float* __restrict__ deg)
{
    extern __shared__ char smem[];
    uint32_t sm = s2u(smem);
    uint32_t* A32   = (uint32_t*)(smem + OFF_A);
    uint32_t* PE32  = (uint32_t*)(smem + OFF_PE);
    const uint2* F0 = (const uint2*)(smem + OFF_B0);
    const uint2* F1 = (const uint2*)(smem + OFF_B1);
    float* sBias    = (float*)(smem + OFF_BIAS);
    int*   sIdx     = (int*)(smem + OFF_IDX);

    int tid  = threadIdx.x;
    int wid  = tid >> 5, lane = tid & 31;
    int mr   = wid & 3,  nc   = wid >> 2;
    int g    = lane >> 2, t   = lane & 3;
    int mbase = mr * 32, nbase = nc * 64;
    int e0   = blockIdx.x * 128;

    // --- stage W1 -> B0, W2 -> B1 via cp.async ---
#pragma unroll
    for (int i = 0; i < 8; i++)
        cp16(sm + OFF_B0 + (i * 256 + tid) * 16, (const char*)g_fW1 + (i * 256 + tid) * 16);
    CP_COMMIT();
#pragma unroll
    for (int i = 0; i < 8; i++)
        cp16(sm + OFF_B1 + (i * 256 + tid) * 16, (const char*)g_fW2 + (i * 256 + tid) * 16);
    CP_COMMIT();

    // --- indices + biases ---
    sIdx[tid] = (tid < 128) ? pe_index[e0 + tid] : pe_index[NE + e0 + (tid - 128)];
#pragma unroll
    for (int i = tid; i < 512; i += 256) {
        int st = i >> 7, c = i & 127;
        float v = (st == 0) ? b_in[c] : (st == 1) ? b1[c]
                : (st == 2) ? (b_in[c] + b2[c])   : bf[c];
        sBias[i] = v;
    }

    // --- build PE tile (fp16, K 24 padded to 32) ---
    {
        int row = tid >> 1, half = tid & 1;
        const float4* pr = (const float4*)(pe_val + (size_t)(e0 + row) * 24) + half * 4;
        uint32_t w[8];
        if (half == 0) {
            float4 v0 = pr[0], v1 = pr[1], v2 = pr[2], v3 = pr[3];
            w[0] = packh2(v0.x, v0.y); w[1] = packh2(v0.z, v0.w);
            w[2] = packh2(v1.x, v1.y); w[3] = packh2(v1.z, v1.w);
            w[4] = packh2(v2.x, v2.y); w[5] = packh2(v2.z, v2.w);
            w[6] = packh2(v3.x, v3.y); w[7] = packh2(v3.z, v3.w);
        } else {
            float4 v0 = pr[0], v1 = pr[1];
            w[0] = packh2(v0.x, v0.y); w[1] = packh2(v0.z, v0.w);
            w[2] = packh2(v1.x, v1.y); w[3] = packh2(v1.z, v1.w);
            w[4] = w[5] = w[6] = w[7] = 0u;
        }
        int sw = (row >> 1) & 3;
        uint32_t* base = PE32 + row * 16;
        int q0 = half * 2, q1 = half * 2 + 1;
        *(uint4*)(base + ((q0 ^ sw) << 2)) = make_uint4(w[0], w[1], w[2], w[3]);
        *(uint4*)(base + ((q1 ^ sw) << 2)) = make_uint4(w[4], w[5], w[6], w[7]);
    }

    float acc[2][8][4];
    __syncthreads();                                 // PE + bias + idx visible

    // ---- stage 1: acc = pe @ Win (Win frags from L2) ----
    zero_acc(acc);
    mma_stagePE(acc, PE32, g_fWin, mbase, nc, g, t, lane);
    epilogueH<0>(acc, sBias, A32, mbase, nbase, g, t);      // A = gelu(x0+b_in)
    CP_WAIT(1);                                              // W1 resident
    __syncthreads();

    // ---- stage 2: acc = A @ W1 ----
    zero_acc(acc);
    mma_stageA<8>(acc, A32, F0, mbase, nc, g, t, lane);
    __syncthreads();                                         // B0+A reads done

    // prefetch Wf -> B0
#pragma unroll
    for (int i = 0; i < 8; i++)
        cp16(sm + OFF_B0 + (i * 256 + tid) * 16, (const char*)g_fWf + (i * 256 + tid) * 16);
    CP_COMMIT();

    epilogueH<0>(acc, sBias + 128, A32, mbase, nbase, g, t); // A = gelu(h+b1)
    CP_WAIT(1);                                              // W2 resident
    __syncthreads();

    // ---- stage 3: acc = A @ W2 + pe @ Win (K-concat residual) ----
    zero_acc(acc);
    mma_stageA<8>(acc, A32, F1, mbase, nc, g, t, lane);
    mma_stagePE(acc, PE32, g_fWin, mbase, nc, g, t, lane);
    __syncthreads();                                         // A reads done
    epilogueH<1>(acc, sBias + 256, A32, mbase, nbase, g, t); // A = res
    CP_WAIT(0);                                              // Wf resident
    __syncthreads();

    // ---- stage 4: acc = A @ Wf ----
    zero_acc(acc);
    mma_stageA<8>(acc, A32, F0, mbase, nc, g, t, lane);
    __syncthreads();                                         // B0 reads done
    float* S = (float*)(smem + OFF_B0);                      // scores overlay 64KB
    epilogueS(acc, sBias + 384, S, mbase, nbase, g, t);
    __syncthreads();

    // ---- scatter: msg = xh[src]*score -> wV[tgt], deg[tgt]++ ----
#pragma unroll 4
    for (int i = 0; i < 16; i++) {
        int e    = wid * 16 + i;
        int tgt  = sIdx[e];
        int srcn = sIdx[128 + e];
        float4 xv = xh4[(size_t)srcn * 32 + lane];
        float4 s4 = *(const float4*)(S + e * 128 + ((lane ^ (e & 7)) << 2));
        red4(wV + (size_t)tgt * 128 + lane * 4,
             xv.x * s4.x, xv.y * s4.y, xv.z * s4.z, xv.w * s4.w);
        if (lane == 0) atomicAdd(deg + tgt, 1.0f);
    }
}

// ---------------- node projection: xh = x @ W_x + b_x (8 nodes/block) ----------------
__global__ void __launch_bounds__(128)
xh_kernel(const float* __restrict__ x, const float* __restrict__ Wx,
          const float* __restrict__ bx, float* __restrict__ xh)
{
    __shared__ float sx[8][64];
    int tid = threadIdx.x;
    int n0  = blockIdx.x * 8;
#pragma unroll
    for (int i = tid; i < 512; i += 128)
        sx[i >> 6][i & 63] = x[(size_t)n0 * 64 + i];
    __syncthreads();
    int c = tid;
    float s[8];
#pragma unroll
    for (int j = 0; j < 8; j++) s[j] = bx[c];
#pragma unroll 8
    for (int k = 0; k < 64; k++) {
        float w = Wx[k * 128 + c];
#pragma unroll
        for (int j = 0; j < 8; j++) s[j] += sx[j][k] * w;
    }
#pragma unroll
    for (int j = 0; j < 8; j++)
        xh[(size_t)(n0 + j) * 128 + c] = s[j];
}

// ---------------- output projection (16 nodes/block, 4 nodes/thread) ----------------
__global__ void __launch_bounds__(256)
out_kernel(const float* __restrict__ wV, const float* __restrict__ deg,
           const float* __restrict__ hb, const float* __restrict__ Wout,
           const float* __restrict__ bout, float* __restrict__ out)
{
    __shared__ float sh[16][128];
    int tid = threadIdx.x;
    int n0  = blockIdx.x * 16;
#pragma unroll
    for (int i = tid; i < 2048; i += 256) {
        int nn = i >> 7, k = i & 127;
        int n  = n0 + nn;
        float d = deg[n];
        float invd = 1.0f / (d > 1.0f ? d : 1.0f);
        sh[nn][k] = wV[(size_t)n * 128 + k] * invd + hb[k];
    }
    __syncthreads();
    int gg = tid >> 6, c = tid & 63;
    float s0 = bout[c], s1 = s0, s2 = s0, s3 = s0;
#pragma unroll 8
    for (int k = 0; k < 128; k++) {
        float w = Wout[k * 64 + c];
        s0 += sh[4*gg+0][k] * w;
        s1 += sh[4*gg+1][k] * w;
        s2 += sh[4*gg+2][k] * w;
        s3 += sh[4*gg+3][k] * w;
    }
    out[(size_t)(n0 + 4*gg + 0) * 64 + c] = s0;
    out[(size_t)(n0 + 4*gg + 1) * 64 + c] = s1;
    out[(size_t)(n0 + 4*gg + 2) * 64 + c] = s2;
    out[(size_t)(n0 + 4*gg + 3) * 64 + c] = s3;
}

// ---------------- launch ----------------
extern "C" void kernel_launch(void* const* d_in, const int* in_sizes, int n_in,
                              void* d_out, int out_size)
{
    const float* x        = (const float*)d_in[0];
    const int*   pe_index = (const int*)  d_in[1];
    const float* pe_val   = (const float*)d_in[2];
    const float* W_in     = (const float*)d_in[3];
    const float* b_in     = (const float*)d_in[4];
    const float* W1       = (const float*)d_in[5];
    const float* b1       = (const float*)d_in[6];
    const float* W2       = (const float*)d_in[7];
    const float* b2       = (const float*)d_in[8];
    const float* W_fin    = (const float*)d_in[9];
    const float* b_fin    = (const float*)d_in[10];
    const float* W_x      = (const float*)d_in[11];
    const float* b_x      = (const float*)d_in[12];
    const float* head_b   = (const float*)d_in[13];
    const float* W_out    = (const float*)d_in[14];
    const float* b_out    = (const float*)d_in[15];
    float* out = (float*)d_out;

    void *p_xh, *p_wV, *p_deg;
    cudaGetSymbolAddress(&p_xh,  g_xh4);
    cudaGetSymbolAddress(&p_wV,  g_wV);
    cudaGetSymbolAddress(&p_deg, g_deg);

    cudaFuncSetAttribute(edge_kernel, cudaFuncAttributeMaxDynamicSharedMemorySize,
                         SMEM_TOT);

    cudaMemsetAsync(p_wV,  0, (size_t)NN * 128 * sizeof(float));
    cudaMemsetAsync(p_deg, 0, (size_t)NN * sizeof(float));

    prep_kernel<<<52, 256>>>(W_in, W1, W2, W_fin);
    xh_kernel<<<NN / 8, 128>>>(x, W_x, b_x, (float*)p_xh);

    edge_kernel<<<NE / 128, 256, SMEM_TOT>>>(pe_index, pe_val,
        b_in, b1, b2, b_fin,
        (const float4*)p_xh, (float*)p_wV, (float*)p_deg);

    out_kernel<<<NN / 16, 256>>>((const float*)p_wV, (const float*)p_deg,
                                 head_b, W_out, b_out, out);
}